// round 1
// baseline (speedup 1.0000x reference)
#include <cuda_runtime.h>
#include <cstdint>

#define MAXN 100000
#define DIM 16
#define EDIM 8
#define HID 64

// Scratch (device globals: allocation-free rule)
__device__ __align__(16) float g_hs[MAXN * DIM];
__device__ __align__(16) float g_conv[MAXN * DIM];

// ---------- packed f32x2 helpers (sm_100+) ----------
__device__ __forceinline__ unsigned long long pack2(float a, float b) {
    unsigned long long r;
    asm("mov.b64 %0, {%1,%2};" : "=l"(r) : "f"(a), "f"(b));
    return r;
}
__device__ __forceinline__ void unpack2(unsigned long long v, float& a, float& b) {
    asm("mov.b64 {%0,%1}, %2;" : "=f"(a), "=f"(b) : "l"(v));
}
__device__ __forceinline__ void fma2(unsigned long long& d, unsigned long long a, unsigned long long b) {
    asm("fma.rn.f32x2 %0, %1, %2, %0;" : "+l"(d) : "l"(a), "l"(b));
}
__device__ __forceinline__ void red_add_v4(float* p, float a, float b, float c, float d) {
    asm volatile("red.global.add.v4.f32 [%0], {%1,%2,%3,%4};"
                 :: "l"(p), "f"(a), "f"(b), "f"(c), "f"(d) : "memory");
}

// ---------- kernel 1: hs = (1+eps)*h ; conv = 0 ----------
__global__ void prep_kernel(const float* __restrict__ h, const float* __restrict__ eps, int n4) {
    int i = blockIdx.x * blockDim.x + threadIdx.x;
    if (i >= n4) return;
    float sc = 1.0f + eps[0];
    float4 v = ((const float4*)h)[i];
    v.x *= sc; v.y *= sc; v.z *= sc; v.w *= sc;
    ((float4*)g_hs)[i] = v;
    ((float4*)g_conv)[i] = make_float4(0.f, 0.f, 0.f, 0.f);
}

// ---------- kernel 2: per-edge NNConv message + scatter-add ----------
// msg[o] = sum_{d,i} relu(ef@We1)[d] * s[i] * We2[d][i*16+o]
__global__ void __launch_bounds__(256) edge_kernel(
    const float* __restrict__ efeat, const int* __restrict__ src, const int* __restrict__ dst,
    const float* __restrict__ We1, const float* __restrict__ We2, int E)
{
    __shared__ __align__(16) float sWe1[EDIM * DIM];           // 512 B
    __shared__ __align__(16) float sWe2[DIM * DIM * DIM];      // 16 KB
    int tid = threadIdx.x;
    if (tid < EDIM * DIM) sWe1[tid] = We1[tid];
    #pragma unroll
    for (int i = tid; i < (DIM * DIM * DIM) / 4; i += 256)
        ((float4*)sWe2)[i] = ((const float4*)We2)[i];
    __syncthreads();

    int e = blockIdx.x * 256 + tid;
    if (e >= E) return;

    // edge features
    float4 e0 = ((const float4*)efeat)[e * 2 + 0];
    float4 e1 = ((const float4*)efeat)[e * 2 + 1];
    float ef[8] = {e0.x, e0.y, e0.z, e0.w, e1.x, e1.y, e1.z, e1.w};

    // gather scaled source node features
    int sn = src[e];
    const float4* hp = (const float4*)&g_hs[sn * DIM];
    float4 s0 = hp[0], s1 = hp[1], s2 = hp[2], s3 = hp[3];
    float s[16] = {s0.x, s0.y, s0.z, s0.w, s1.x, s1.y, s1.z, s1.w,
                   s2.x, s2.y, s2.z, s2.w, s3.x, s3.y, s3.z, s3.w};

    unsigned long long acc[8];
    #pragma unroll
    for (int k = 0; k < 8; k++) acc[k] = 0ull;

    const ulonglong2* W2v = (const ulonglong2*)sWe2;  // 16 B = 4 floats each

    #pragma unroll 1
    for (int d = 0; d < 16; d++) {
        // recompute hid[d] on the fly (keeps everything in registers, no local mem)
        float a = ef[0] * sWe1[d];
        #pragma unroll
        for (int j = 1; j < 8; j++) a = fmaf(ef[j], sWe1[j * 16 + d], a);
        float hd = fmaxf(a, 0.0f);

        const ulonglong2* row = W2v + d * 64;   // d*256 floats
        #pragma unroll
        for (int i = 0; i < 16; i++) {
            float w = hd * s[i];
            unsigned long long w2 = pack2(w, w);
            ulonglong2 p0 = row[i * 4 + 0];
            ulonglong2 p1 = row[i * 4 + 1];
            ulonglong2 p2 = row[i * 4 + 2];
            ulonglong2 p3 = row[i * 4 + 3];
            fma2(acc[0], w2, p0.x); fma2(acc[1], w2, p0.y);
            fma2(acc[2], w2, p1.x); fma2(acc[3], w2, p1.y);
            fma2(acc[4], w2, p2.x); fma2(acc[5], w2, p2.y);
            fma2(acc[6], w2, p3.x); fma2(acc[7], w2, p3.y);
        }
    }

    float m[16];
    #pragma unroll
    for (int k = 0; k < 8; k++) unpack2(acc[k], m[2 * k], m[2 * k + 1]);

    int dn = dst[e];
    float* op = &g_conv[dn * DIM];
    red_add_v4(op + 0,  m[0],  m[1],  m[2],  m[3]);
    red_add_v4(op + 4,  m[4],  m[5],  m[6],  m[7]);
    red_add_v4(op + 8,  m[8],  m[9],  m[10], m[11]);
    red_add_v4(op + 12, m[12], m[13], m[14], m[15]);
}

// ---------- kernel 3: node MLP (16->64 leaky, 64->64) + LayerNorm(64) ----------
// 16 nodes per block of 256 threads; 16 threads per node, 4 outputs per thread.
__global__ void __launch_bounds__(256) node_kernel(
    const float* __restrict__ W1, const float* __restrict__ b1,
    const float* __restrict__ W2, const float* __restrict__ b2,
    const float* __restrict__ lg, const float* __restrict__ lb,
    float* __restrict__ out, int N, int ntiles)
{
    __shared__ __align__(16) float sW1[DIM * HID];    // 4 KB
    __shared__ __align__(16) float sW2[HID * HID];    // 16 KB
    __shared__ __align__(16) float sb1[HID], sb2[HID], sg[HID], sb[HID];
    __shared__ __align__(16) float shf[16 * DIM];     // per-tile hf
    __shared__ __align__(16) float sx1[16 * 68];      // padded stride 68

    int tid = threadIdx.x;
    for (int i = tid; i < DIM * HID; i += 256) sW1[i] = W1[i];
    for (int i = tid; i < HID * HID; i += 256) sW2[i] = W2[i];
    if (tid < HID) { sb1[tid] = b1[tid]; sb2[tid] = b2[tid]; sg[tid] = lg[tid]; sb[tid] = lb[tid]; }
    __syncthreads();

    int node_l = tid >> 4;    // 0..15
    int t = tid & 15;         // 0..15  -> outputs j = 4t..4t+3

    const ulonglong2* W1v = (const ulonglong2*)sW1;
    const ulonglong2* W2v = (const ulonglong2*)sW2;

    for (int tile = blockIdx.x; tile < ntiles; tile += gridDim.x) {
        int n = tile * 16 + node_l;

        // stage hf = hs + conv   (thread (node_l, t) loads feature t of its node)
        float v = 0.0f;
        if (n < N) v = g_hs[n * DIM + t] + g_conv[n * DIM + t];
        shf[node_l * DIM + t] = v;
        __syncthreads();

        // layer 1: x1[j] = leaky_relu(b1[j] + sum_i hf[i]*W1[i][j])
        unsigned long long a0 = pack2(sb1[4 * t + 0], sb1[4 * t + 1]);
        unsigned long long a1 = pack2(sb1[4 * t + 2], sb1[4 * t + 3]);
        #pragma unroll
        for (int i = 0; i < DIM; i++) {
            float hfi = shf[node_l * DIM + i];
            unsigned long long h2 = pack2(hfi, hfi);
            ulonglong2 wr = W1v[i * 16 + t];
            fma2(a0, h2, wr.x);
            fma2(a1, h2, wr.y);
        }
        float x0, x1, x2, x3;
        unpack2(a0, x0, x1);
        unpack2(a1, x2, x3);
        x0 = fmaxf(x0, 0.f) + 0.01f * fminf(x0, 0.f);
        x1 = fmaxf(x1, 0.f) + 0.01f * fminf(x1, 0.f);
        x2 = fmaxf(x2, 0.f) + 0.01f * fminf(x2, 0.f);
        x3 = fmaxf(x3, 0.f) + 0.01f * fminf(x3, 0.f);
        ((float4*)&sx1[node_l * 68])[t] = make_float4(x0, x1, x2, x3);
        __syncthreads();

        // layer 2: x2[j] = b2[j] + sum_k x1[k]*W2[k][j]
        unsigned long long c0 = pack2(sb2[4 * t + 0], sb2[4 * t + 1]);
        unsigned long long c1 = pack2(sb2[4 * t + 2], sb2[4 * t + 3]);
        const float* x1p = &sx1[node_l * 68];
        #pragma unroll
        for (int k = 0; k < HID; k++) {
            float xk = x1p[k];
            unsigned long long xk2 = pack2(xk, xk);
            ulonglong2 wr = W2v[k * 16 + t];
            fma2(c0, xk2, wr.x);
            fma2(c1, xk2, wr.y);
        }
        float y0, y1, y2, y3;
        unpack2(c0, y0, y1);
        unpack2(c1, y2, y3);

        // LayerNorm over the node's 64 outputs (16 threads = half warp per node)
        float ssum = y0 + y1 + y2 + y3;
        float ssq = y0 * y0 + y1 * y1 + y2 * y2 + y3 * y3;
        #pragma unroll
        for (int m = 8; m >= 1; m >>= 1) {
            ssum += __shfl_xor_sync(0xffffffffu, ssum, m);
            ssq  += __shfl_xor_sync(0xffffffffu, ssq, m);
        }
        float mu = ssum * (1.0f / 64.0f);
        float var = ssq * (1.0f / 64.0f) - mu * mu;
        float rstd = rsqrtf(var + 1e-5f);

        if (n < N) {
            float4 gg = ((const float4*)sg)[t];
            float4 bb = ((const float4*)sb)[t];
            float4 o;
            o.x = (y0 - mu) * rstd * gg.x + bb.x;
            o.y = (y1 - mu) * rstd * gg.y + bb.y;
            o.z = (y2 - mu) * rstd * gg.z + bb.z;
            o.w = (y3 - mu) * rstd * gg.w + bb.w;
            ((float4*)out)[n * 16 + t] = o;
        }
        __syncthreads();   // protect shf/sx1 reuse
    }
}

extern "C" void kernel_launch(void* const* d_in, const int* in_sizes, int n_in,
                              void* d_out, int out_size) {
    const float* h     = (const float*)d_in[0];
    const float* ef0   = (const float*)d_in[1];
    const float* ef1   = (const float*)d_in[2];
    const int*   src0  = (const int*)d_in[3];
    const int*   dst0  = (const int*)d_in[4];
    const int*   src1  = (const int*)d_in[5];
    const int*   dst1  = (const int*)d_in[6];
    const float* We1_0 = (const float*)d_in[7];
    const float* We2_0 = (const float*)d_in[8];
    const float* We1_1 = (const float*)d_in[9];
    const float* We2_1 = (const float*)d_in[10];
    const float* W1    = (const float*)d_in[11];
    const float* b1    = (const float*)d_in[12];
    const float* W2    = (const float*)d_in[13];
    const float* b2    = (const float*)d_in[14];
    const float* lg    = (const float*)d_in[15];
    const float* lb    = (const float*)d_in[16];
    const float* eps   = (const float*)d_in[17];

    int N  = in_sizes[0] / DIM;
    int E0 = in_sizes[3];
    int E1 = in_sizes[5];

    int n4 = N * DIM / 4;
    prep_kernel<<<(n4 + 255) / 256, 256>>>(h, eps, n4);

    edge_kernel<<<(E0 + 255) / 256, 256>>>(ef0, src0, dst0, We1_0, We2_0, E0);
    edge_kernel<<<(E1 + 255) / 256, 256>>>(ef1, src1, dst1, We1_1, We2_1, E1);

    int ntiles = (N + 15) / 16;
    int grid = ntiles < 1184 ? ntiles : 1184;
    node_kernel<<<grid, 256>>>(W1, b1, W2, b2, lg, lb, (float*)d_out, N, ntiles);
}

// round 2
// speedup vs baseline: 1.2339x; 1.2339x over previous
#include <cuda_runtime.h>
#include <cstdint>

#define MAXN 100000
#define DIM 16
#define EDIM 8
#define HID 64

// Scratch (device globals: allocation-free rule)
__device__ __align__(16) float g_hs[MAXN * DIM];
__device__ __align__(16) float g_conv[MAXN * DIM];

// ---------- packed f32x2 helpers (sm_100+) ----------
__device__ __forceinline__ unsigned long long pack2(float a, float b) {
    unsigned long long r;
    asm("mov.b64 %0, {%1,%2};" : "=l"(r) : "f"(a), "f"(b));
    return r;
}
__device__ __forceinline__ void unpack2(unsigned long long v, float& a, float& b) {
    asm("mov.b64 {%0,%1}, %2;" : "=f"(a), "=f"(b) : "l"(v));
}
__device__ __forceinline__ void fma2(unsigned long long& d, unsigned long long a, unsigned long long b) {
    asm("fma.rn.f32x2 %0, %1, %2, %0;" : "+l"(d) : "l"(a), "l"(b));
}
__device__ __forceinline__ unsigned long long mul2(unsigned long long a, unsigned long long b) {
    unsigned long long r;
    asm("mul.rn.f32x2 %0, %1, %2;" : "=l"(r) : "l"(a), "l"(b));
    return r;
}
__device__ __forceinline__ void red_add_v4(float* p, float a, float b, float c, float d) {
    asm volatile("red.global.add.v4.f32 [%0], {%1,%2,%3,%4};"
                 :: "l"(p), "f"(a), "f"(b), "f"(c), "f"(d) : "memory");
}

// ---------- kernel 1: hs = (1+eps)*h ; conv = 0 ----------
__global__ void prep_kernel(const float* __restrict__ h, const float* __restrict__ eps, int n4) {
    int i = blockIdx.x * blockDim.x + threadIdx.x;
    if (i >= n4) return;
    float sc = 1.0f + eps[0];
    float4 v = ((const float4*)h)[i];
    v.x *= sc; v.y *= sc; v.z *= sc; v.w *= sc;
    ((float4*)g_hs)[i] = v;
    ((float4*)g_conv)[i] = make_float4(0.f, 0.f, 0.f, 0.f);
}

// ---------- kernel 2: per-edge NNConv message + scatter-add ----------
// msg[o] = sum_{d,i} relu(ef@We1)[d] * s[i] * We2[d][i*16+o]
__global__ void __launch_bounds__(256) edge_kernel(
    const float* __restrict__ efeat, const int* __restrict__ src, const int* __restrict__ dst,
    const float* __restrict__ We1, const float* __restrict__ We2, int E)
{
    __shared__ __align__(16) float sWe1[EDIM * DIM];           // 512 B
    __shared__ __align__(16) float sWe2[DIM * DIM * DIM];      // 16 KB
    int tid = threadIdx.x;
    if (tid < EDIM * DIM) sWe1[tid] = We1[tid];
    #pragma unroll
    for (int i = tid; i < (DIM * DIM * DIM) / 4; i += 256)
        ((float4*)sWe2)[i] = ((const float4*)We2)[i];
    __syncthreads();

    int e = blockIdx.x * 256 + tid;
    if (e >= E) return;

    // edge features
    float4 e0 = ((const float4*)efeat)[e * 2 + 0];
    float4 e1 = ((const float4*)efeat)[e * 2 + 1];
    float ef[8] = {e0.x, e0.y, e0.z, e0.w, e1.x, e1.y, e1.z, e1.w};

    // gather scaled source node features, pre-pack into f32x2 broadcast pairs
    int sn = src[e];
    const float4* hp = (const float4*)&g_hs[sn * DIM];
    unsigned long long s2[16];
    #pragma unroll
    for (int q = 0; q < 4; q++) {
        float4 sv = hp[q];
        s2[4 * q + 0] = pack2(sv.x, sv.x);
        s2[4 * q + 1] = pack2(sv.y, sv.y);
        s2[4 * q + 2] = pack2(sv.z, sv.z);
        s2[4 * q + 3] = pack2(sv.w, sv.w);
    }

    unsigned long long acc[8];
    #pragma unroll
    for (int k = 0; k < 8; k++) acc[k] = 0ull;

    const ulonglong2* W2v = (const ulonglong2*)sWe2;  // 16 B = 4 floats each

    #pragma unroll 1
    for (int d = 0; d < 16; d++) {
        // recompute hid[d] on the fly
        float a = ef[0] * sWe1[d];
        #pragma unroll
        for (int j = 1; j < 8; j++) a = fmaf(ef[j], sWe1[j * 16 + d], a);
        float hd = fmaxf(a, 0.0f);
        unsigned long long hd2 = pack2(hd, hd);

        const ulonglong2* row = W2v + d * 64;   // d*256 floats
        #pragma unroll
        for (int i = 0; i < 16; i++) {
            unsigned long long w2 = mul2(hd2, s2[i]);
            ulonglong2 p0 = row[i * 4 + 0];
            ulonglong2 p1 = row[i * 4 + 1];
            ulonglong2 p2 = row[i * 4 + 2];
            ulonglong2 p3 = row[i * 4 + 3];
            fma2(acc[0], w2, p0.x); fma2(acc[1], w2, p0.y);
            fma2(acc[2], w2, p1.x); fma2(acc[3], w2, p1.y);
            fma2(acc[4], w2, p2.x); fma2(acc[5], w2, p2.y);
            fma2(acc[6], w2, p3.x); fma2(acc[7], w2, p3.y);
        }
    }

    float m[16];
    #pragma unroll
    for (int k = 0; k < 8; k++) unpack2(acc[k], m[2 * k], m[2 * k + 1]);

    int dn = dst[e];
    float* op = &g_conv[dn * DIM];
    red_add_v4(op + 0,  m[0],  m[1],  m[2],  m[3]);
    red_add_v4(op + 4,  m[4],  m[5],  m[6],  m[7]);
    red_add_v4(op + 8,  m[8],  m[9],  m[10], m[11]);
    red_add_v4(op + 12, m[12], m[13], m[14], m[15]);
}

// ---------- kernel 3: node MLP (16->64 leaky, 64->64) + LayerNorm(64) ----------
// 64 nodes per tile per block of 256 threads.
// 16 groups x 16 threads; group g owns 4 nodes, thread t owns outputs 4t..4t+3.
// Activations staged TRANSPOSED in smem so the per-k activation read is one
// broadcast float4 covering the group's 4 nodes; weight LDS.128 amortized 4x.
__global__ void __launch_bounds__(256) node_kernel(
    const float* __restrict__ W1, const float* __restrict__ b1,
    const float* __restrict__ W2, const float* __restrict__ b2,
    const float* __restrict__ lg, const float* __restrict__ lb,
    float* __restrict__ out, int N, int ntiles)
{
    __shared__ __align__(16) float sW1[DIM * HID];    // 4 KB
    __shared__ __align__(16) float sW2[HID * HID];    // 16 KB
    __shared__ __align__(16) float sb1[HID], sb2[HID], sg[HID], sb[HID];
    __shared__ __align__(16) float shf_t[DIM][68];    // hf transposed [feat][node]
    __shared__ __align__(16) float sx1t[HID][68];     // x1 transposed [k][node]

    int tid = threadIdx.x;
    for (int i = tid; i < DIM * HID; i += 256) sW1[i] = W1[i];
    for (int i = tid; i < HID * HID; i += 256) sW2[i] = W2[i];
    if (tid < HID) { sb1[tid] = b1[tid]; sb2[tid] = b2[tid]; sg[tid] = lg[tid]; sb[tid] = lb[tid]; }
    __syncthreads();

    int g = tid >> 4;     // group 0..15 -> nodes 4g..4g+3 within tile
    int t = tid & 15;     // outputs 4t..4t+3

    // staging-load mapping: 4 threads per node, each loads 4 consecutive feats
    int ld_node = tid >> 2;     // 0..63
    int ld_part = tid & 3;      // feature block

    const ulonglong2* W1v = (const ulonglong2*)sW1;
    const ulonglong2* W2v = (const ulonglong2*)sW2;

    for (int tile = blockIdx.x; tile < ntiles; tile += gridDim.x) {
        // ---- stage hf = hs + conv, transposed ----
        {
            int n = tile * 64 + ld_node;
            float4 a = make_float4(0.f, 0.f, 0.f, 0.f);
            if (n < N) {
                float4 hv = ((const float4*)g_hs)[n * 4 + ld_part];
                float4 cv = ((const float4*)g_conv)[n * 4 + ld_part];
                a.x = hv.x + cv.x; a.y = hv.y + cv.y;
                a.z = hv.z + cv.z; a.w = hv.w + cv.w;
            }
            shf_t[ld_part * 4 + 0][ld_node] = a.x;
            shf_t[ld_part * 4 + 1][ld_node] = a.y;
            shf_t[ld_part * 4 + 2][ld_node] = a.z;
            shf_t[ld_part * 4 + 3][ld_node] = a.w;
        }
        __syncthreads();

        // ---- layer 1: x1 = leaky_relu(hf @ W1 + b1), 4 nodes per thread ----
        unsigned long long a00, a01, a10, a11, a20, a21, a30, a31;
        {
            unsigned long long bb0 = pack2(sb1[4 * t + 0], sb1[4 * t + 1]);
            unsigned long long bb1 = pack2(sb1[4 * t + 2], sb1[4 * t + 3]);
            a00 = bb0; a01 = bb1; a10 = bb0; a11 = bb1;
            a20 = bb0; a21 = bb1; a30 = bb0; a31 = bb1;
        }
        #pragma unroll
        for (int i = 0; i < DIM; i++) {
            ulonglong2 w = W1v[i * 16 + t];
            float4 hv = *(const float4*)&shf_t[i][g * 4];
            unsigned long long h0 = pack2(hv.x, hv.x);
            unsigned long long h1 = pack2(hv.y, hv.y);
            unsigned long long h2 = pack2(hv.z, hv.z);
            unsigned long long h3 = pack2(hv.w, hv.w);
            fma2(a00, h0, w.x); fma2(a01, h0, w.y);
            fma2(a10, h1, w.x); fma2(a11, h1, w.y);
            fma2(a20, h2, w.x); fma2(a21, h2, w.y);
            fma2(a30, h3, w.x); fma2(a31, h3, w.y);
        }
        // leaky relu + transposed store
        {
            float x[4][4];
            unpack2(a00, x[0][0], x[0][1]); unpack2(a01, x[0][2], x[0][3]);
            unpack2(a10, x[1][0], x[1][1]); unpack2(a11, x[1][2], x[1][3]);
            unpack2(a20, x[2][0], x[2][1]); unpack2(a21, x[2][2], x[2][3]);
            unpack2(a30, x[3][0], x[3][1]); unpack2(a31, x[3][2], x[3][3]);
            #pragma unroll
            for (int n = 0; n < 4; n++)
                #pragma unroll
                for (int j = 0; j < 4; j++)
                    x[n][j] = fmaxf(x[n][j], 0.f) + 0.01f * fminf(x[n][j], 0.f);
            #pragma unroll
            for (int j = 0; j < 4; j++)
                *(float4*)&sx1t[4 * t + j][g * 4] =
                    make_float4(x[0][j], x[1][j], x[2][j], x[3][j]);
        }
        __syncthreads();

        // ---- layer 2: y = x1 @ W2 + b2, 4 nodes per thread ----
        unsigned long long c00, c01, c10, c11, c20, c21, c30, c31;
        {
            unsigned long long bb0 = pack2(sb2[4 * t + 0], sb2[4 * t + 1]);
            unsigned long long bb1 = pack2(sb2[4 * t + 2], sb2[4 * t + 3]);
            c00 = bb0; c01 = bb1; c10 = bb0; c11 = bb1;
            c20 = bb0; c21 = bb1; c30 = bb0; c31 = bb1;
        }
        #pragma unroll
        for (int k = 0; k < HID; k++) {
            ulonglong2 w = W2v[k * 16 + t];
            float4 xv = *(const float4*)&sx1t[k][g * 4];
            unsigned long long x0 = pack2(xv.x, xv.x);
            unsigned long long x1 = pack2(xv.y, xv.y);
            unsigned long long x2 = pack2(xv.z, xv.z);
            unsigned long long x3 = pack2(xv.w, xv.w);
            fma2(c00, x0, w.x); fma2(c01, x0, w.y);
            fma2(c10, x1, w.x); fma2(c11, x1, w.y);
            fma2(c20, x2, w.x); fma2(c21, x2, w.y);
            fma2(c30, x3, w.x); fma2(c31, x3, w.y);
        }

        float y[4][4];
        unpack2(c00, y[0][0], y[0][1]); unpack2(c01, y[0][2], y[0][3]);
        unpack2(c10, y[1][0], y[1][1]); unpack2(c11, y[1][2], y[1][3]);
        unpack2(c20, y[2][0], y[2][1]); unpack2(c21, y[2][2], y[2][3]);
        unpack2(c30, y[3][0], y[3][1]); unpack2(c31, y[3][2], y[3][3]);

        // ---- LayerNorm per node across the 16 threads of the group ----
        float4 gg = ((const float4*)sg)[t];
        float4 bb = ((const float4*)sb)[t];
        #pragma unroll
        for (int n = 0; n < 4; n++) {
            float ssum = y[n][0] + y[n][1] + y[n][2] + y[n][3];
            float ssq  = y[n][0] * y[n][0] + y[n][1] * y[n][1]
                       + y[n][2] * y[n][2] + y[n][3] * y[n][3];
            #pragma unroll
            for (int m = 8; m >= 1; m >>= 1) {
                ssum += __shfl_xor_sync(0xffffffffu, ssum, m);
                ssq  += __shfl_xor_sync(0xffffffffu, ssq, m);
            }
            float mu = ssum * (1.0f / 64.0f);
            float var = ssq * (1.0f / 64.0f) - mu * mu;
            float rstd = rsqrtf(var + 1e-5f);

            int node = tile * 64 + g * 4 + n;
            if (node < N) {
                float4 o;
                o.x = (y[n][0] - mu) * rstd * gg.x + bb.x;
                o.y = (y[n][1] - mu) * rstd * gg.y + bb.y;
                o.z = (y[n][2] - mu) * rstd * gg.z + bb.z;
                o.w = (y[n][3] - mu) * rstd * gg.w + bb.w;
                ((float4*)out)[node * 16 + t] = o;
            }
        }
        __syncthreads();   // protect shf_t/sx1t reuse
    }
}

extern "C" void kernel_launch(void* const* d_in, const int* in_sizes, int n_in,
                              void* d_out, int out_size) {
    const float* h     = (const float*)d_in[0];
    const float* ef0   = (const float*)d_in[1];
    const float* ef1   = (const float*)d_in[2];
    const int*   src0  = (const int*)d_in[3];
    const int*   dst0  = (const int*)d_in[4];
    const int*   src1  = (const int*)d_in[5];
    const int*   dst1  = (const int*)d_in[6];
    const float* We1_0 = (const float*)d_in[7];
    const float* We2_0 = (const float*)d_in[8];
    const float* We1_1 = (const float*)d_in[9];
    const float* We2_1 = (const float*)d_in[10];
    const float* W1    = (const float*)d_in[11];
    const float* b1    = (const float*)d_in[12];
    const float* W2    = (const float*)d_in[13];
    const float* b2    = (const float*)d_in[14];
    const float* lg    = (const float*)d_in[15];
    const float* lb    = (const float*)d_in[16];
    const float* eps   = (const float*)d_in[17];

    int N  = in_sizes[0] / DIM;
    int E0 = in_sizes[3];
    int E1 = in_sizes[5];

    int n4 = N * DIM / 4;
    prep_kernel<<<(n4 + 255) / 256, 256>>>(h, eps, n4);

    edge_kernel<<<(E0 + 255) / 256, 256>>>(ef0, src0, dst0, We1_0, We2_0, E0);
    edge_kernel<<<(E1 + 255) / 256, 256>>>(ef1, src1, dst1, We1_1, We2_1, E1);

    int ntiles = (N + 63) / 64;
    int grid = ntiles < 1184 ? ntiles : 1184;
    node_kernel<<<grid, 256>>>(W1, b1, W2, b2, lg, lb, (float*)d_out, N, ntiles);
}